// round 11
// baseline (speedup 1.0000x reference)
#include <cuda_runtime.h>
#include <cstdint>

// out = X * W[idx][0] + Y * W[idx][1], idx = reward[b,s] in {0,1}
// X,Y: (4,4096,2048) fp32; reward: (4,4096,1) int32; W: (2,2) fp32.
//
// FINAL KERNEL (R6 winner, confirmed by re-bench in R9).
// HBM-bound blend at the measured controller ceiling for a 2R:1W stream:
//   - one block = one (b,s) row = 512 contiguous float4
//   - 2 float4/thread at stride 256 -> every LDG/STG is a fully coalesced
//     512B warp wavefront
//   - 4 front-batched loads/thread (MLP=4 = peak of measured MLP sweep:
//     MLP2 -> 74.7% DRAM, MLP4 -> 85%, MLP8 -> 79% [L1tex queue contention])
//   - single uniform reward load per block; W gather from L1
//   - default cache policy (R7: __ldcs/__stcs regressed; R10: __ldlu neutral)
//   - flat 16384-CTA grid (R8: persistent grid regressed via loop
//     serialization of the load stream)
// Measured: 52.1-52.9us kernel, 6655-6757 GB/s (83-85% of 8TB/s spec),
// all compute pipes <7%, rel_err 3.6e-08.

__global__ __launch_bounds__(256)
void blend_kernel_row(const float4* __restrict__ X,
                      const float4* __restrict__ Y,
                      const int* __restrict__ reward,
                      const float* __restrict__ W,
                      float4* __restrict__ out)
{
    int base = blockIdx.x * 512 + threadIdx.x;   // row = blockIdx.x

    int idx = (reward[blockIdx.x] != 0) ? 1 : 0; // uniform across block
    float a = W[2 * idx];
    float b = W[2 * idx + 1];

    // Front-batch 4 global loads (MLP=4).
    float4 x0 = X[base];
    float4 x1 = X[base + 256];
    float4 y0 = Y[base];
    float4 y1 = Y[base + 256];

    float4 o0, o1;
    o0.x = fmaf(x0.x, a, y0.x * b);
    o0.y = fmaf(x0.y, a, y0.y * b);
    o0.z = fmaf(x0.z, a, y0.z * b);
    o0.w = fmaf(x0.w, a, y0.w * b);
    o1.x = fmaf(x1.x, a, y1.x * b);
    o1.y = fmaf(x1.y, a, y1.y * b);
    o1.z = fmaf(x1.z, a, y1.z * b);
    o1.w = fmaf(x1.w, a, y1.w * b);

    out[base]       = o0;
    out[base + 256] = o1;
}

extern "C" void kernel_launch(void* const* d_in, const int* in_sizes, int n_in,
                              void* d_out, int out_size)
{
    const float4* X      = (const float4*)d_in[0];
    const float4* Y      = (const float4*)d_in[1];
    const int*    reward = (const int*)d_in[2];
    const float*  W      = (const float*)d_in[3];
    float4*       out    = (float4*)d_out;

    int n  = out_size;          // 4*4096*2048 = 33554432 fp32
    int n4 = n / 4;             // 8388608 float4
    int blocks = n4 / 512;      // 16384 blocks, one row each (exact)

    blend_kernel_row<<<blocks, 256>>>(X, Y, reward, W, out);
}